// round 8
// baseline (speedup 1.0000x reference)
#include <cuda_runtime.h>
#include <math.h>

// ---------------------------------------------------------------------------
// SPFBlock fused kernel v2, sm_103a
// Changes vs v1: main GEMM uses packed fma.rn.f32x2 (2 MACs/instr), broadcast-
// friendly smem mapping (8pos x 2out per thread), g_t stored channel-major,
// register-prefetched W chunks, 64-pos blocks at 2 blocks/SM.
// ---------------------------------------------------------------------------

#define BATCH   4
#define CIN     128
#define LTOT    16384           // H*W
#define NHEAD   4
#define NPH     32
#define MTRI    528
#define CPOOL   2112
#define DIMO    64
#define KC      64              // 2112 = 33 * 64

// ------------------------- device scratch (static) -------------------------
__device__ float g_t[BATCH * CIN * LTOT];       // shuffled LN'd t, [b][c][pos]
__device__ float g_e[BATCH * LTOT * NHEAD];     // exp(logit)
__device__ float g_wT[CPOOL * DIMO];            // dr_w transposed [k][o]
__device__ float g_fc1T[DIMO * DIMO];           // fc1_w transposed [c][j]
__device__ float g_umid[BATCH * CIN];           // t at mid, shuffled order
__device__ float g_invnmid[BATCH * NHEAD];      // 1/||y_mid||
__device__ float g_sumexp[BATCH * NHEAD];       // softmax denominators
__device__ uchar2 g_ij[CPOOL];                  // tri indices (i,j) + head off

// ------------------------------ f32x2 helpers ------------------------------
__device__ __forceinline__ unsigned long long dup2(float x) {
    unsigned long long r;
    asm("mov.b64 %0, {%1, %1};" : "=l"(r) : "f"(x));
    return r;
}
__device__ __forceinline__ void ffma2(unsigned long long& acc,
                                      unsigned long long a,
                                      unsigned long long b) {
    asm("fma.rn.f32x2 %0, %1, %2, %0;" : "+l"(acc) : "l"(a), "l"(b));
}
__device__ __forceinline__ float2 unpk(unsigned long long v) {
    float2 r;
    asm("mov.b64 {%0, %1}, %2;" : "=f"(r.x), "=f"(r.y) : "l"(v));
    return r;
}

// ------------------------------- init kernel -------------------------------
__global__ void k_init(const float* __restrict__ dr_w,
                       const float* __restrict__ fc1_w) {
    int tid = blockIdx.x * blockDim.x + threadIdx.x;
    int nth = gridDim.x * blockDim.x;
    for (int idx = tid; idx < CPOOL * DIMO; idx += nth) {
        int k = idx >> 6, o = idx & 63;
        g_wT[idx] = dr_w[o * CPOOL + k];
    }
    for (int idx = tid; idx < DIMO * DIMO; idx += nth) {
        int c = idx >> 6, j = idx & 63;
        g_fc1T[idx] = fc1_w[j * DIMO + c];
    }
    if (blockIdx.x == 0) {
        for (int m = threadIdx.x; m < MTRI; m += blockDim.x) {
            int i = 0, off = 0;
            while (off + (NPH - i) <= m) { off += NPH - i; i++; }
            int j = i + (m - off);
            #pragma unroll
            for (int h = 0; h < NHEAD; h++) {
                uchar2 v;
                v.x = (unsigned char)(h * NPH + i);
                v.y = (unsigned char)(h * NPH + j);
                g_ij[h * MTRI + m] = v;
            }
        }
        if (threadIdx.x < BATCH * NHEAD) g_sumexp[threadIdx.x] = 0.0f;
    }
}

// ------------------------------- mid kernel --------------------------------
__global__ void k_mid(const float* __restrict__ x,
                      const float* __restrict__ n1w,
                      const float* __restrict__ n1b) {
    __shared__ float red[CIN];
    __shared__ float us[CIN];
    int b = blockIdx.x, tid = threadIdx.x;
    float v = x[((size_t)b * CIN + tid) * LTOT + (LTOT / 2)];
    red[tid] = v;
    __syncthreads();
    for (int o = 64; o; o >>= 1) { if (tid < o) red[tid] += red[tid + o]; __syncthreads(); }
    float mu = red[0] * (1.0f / 128.0f);
    __syncthreads();
    red[tid] = v * v;
    __syncthreads();
    for (int o = 64; o; o >>= 1) { if (tid < o) red[tid] += red[tid + o]; __syncthreads(); }
    float var = red[0] * (1.0f / 128.0f) - mu * mu;
    float rstd = rsqrtf(var + 1e-5f);
    float xn = (v - mu) * rstd * n1w[tid] + n1b[tid];
    int cp = ((tid & 3) << 5) + (tid >> 2);          // shuffled channel
    us[cp] = xn;
    g_umid[b * CIN + cp] = xn;
    __syncthreads();
    if (tid < NHEAD) {
        float uu = 0.f, s4 = 0.f;
        #pragma unroll
        for (int i = 0; i < NPH; i++) {
            float u = us[tid * NPH + i];
            float u2 = u * u;
            uu += u2; s4 += u2 * u2;
        }
        g_invnmid[b * NHEAD + tid] = rsqrtf(0.5f * (uu * uu + s4));
    }
}

// -------------------------------- LN kernel --------------------------------
// 128 positions per block; stores t CHANNEL-MAJOR now.
__global__ void k_ln(const float* __restrict__ x,
                     const float* __restrict__ n1w,
                     const float* __restrict__ n1b) {
    extern __shared__ float sm[];
    float* xs   = sm;                       // 128*129
    float* su   = sm + 128 * 129;           // 128
    float* swv  = su + 128;                 // 128
    float* sbv  = swv + 128;                // 128
    float* sAcc = sbv + 128;                // 4

    int tid = threadIdx.x;
    int blk = blockIdx.x;
    int b   = blk >> 7;
    int p0  = (blk & 127) << 7;

    su[tid] = g_umid[b * CIN + tid];
    {
        int c = ((tid & 31) << 2) + (tid >> 5);   // inverse shuffle
        swv[tid] = n1w[c];
        sbv[tid] = n1b[c];
    }
    if (tid < NHEAD) sAcc[tid] = 0.0f;

    const float* xb = x + (size_t)b * CIN * LTOT + p0;
    #pragma unroll 4
    for (int cc = 0; cc < CIN; cc++) {
        float v = xb[(size_t)cc * LTOT + tid];
        int cp = ((cc & 3) << 5) + (cc >> 2);
        xs[tid * 129 + cp] = v;
    }
    __syncthreads();

    float* row = xs + tid * 129;
    float s = 0.f, s2 = 0.f;
    #pragma unroll 8
    for (int c = 0; c < CIN; c++) { float v = row[c]; s += v; s2 += v * v; }
    float mu   = s  * (1.0f / 128.0f);
    float var  = s2 * (1.0f / 128.0f) - mu * mu;
    float rstd = rsqrtf(var + 1e-5f);

    int gp = b * LTOT + p0 + tid;
    #pragma unroll
    for (int h = 0; h < NHEAD; h++) {
        float duv = 0.f, dvv = 0.f, suv = 0.f, sv4 = 0.f;
        #pragma unroll 8
        for (int i = 0; i < NPH; i++) {
            int c = h * NPH + i;
            float v = (row[c] - mu) * rstd * swv[c] + sbv[c];
            row[c] = v;
            float u  = su[c];
            float uv = u * v;
            float v2 = v * v;
            duv += uv;
            dvv += v2;
            suv += uv * uv;
            sv4 += v2 * v2;
        }
        float ny2   = 0.5f * (dvv * dvv + sv4);
        float logit = 0.5f * (duv * duv + suv) * rsqrtf(ny2) * g_invnmid[b * NHEAD + h];
        float e = expf(logit);
        g_e[gp * NHEAD + h] = e;
        float we = e;
        #pragma unroll
        for (int o = 16; o; o >>= 1) we += __shfl_xor_sync(0xffffffffu, we, o);
        if ((tid & 31) == 0) atomicAdd(&sAcc[h], we);
    }
    __syncthreads();
    if (tid < NHEAD) atomicAdd(&g_sumexp[b * NHEAD + tid], sAcc[tid]);

    // channel-major coalesced store
    float* tb = g_t + (size_t)b * CIN * LTOT + p0;
    #pragma unroll 4
    for (int c = 0; c < CIN; c++) {
        tb[(size_t)c * LTOT + tid] = xs[tid * 129 + c];
    }
}

// ------------------------------- main kernel -------------------------------
// 64 positions x 64 outputs per block, 256 threads.
// Thread tile: 8 pos x 2 out, accumulated in f32x2 pairs (fma.rn.f32x2).
__global__ __launch_bounds__(256, 2) void k_main(const float* __restrict__ dr_b,
                                                 const float* __restrict__ n2w,
                                                 const float* __restrict__ n2b,
                                                 const float* __restrict__ fc1_b,
                                                 float* __restrict__ out) {
    extern __shared__ float sm[];
    float* A   = sm;              // 128*68 = 8704 floats (sTt; later zt+zo)
    float* sPF = sm + 8704;       // 64*64 = 4096 (pf chunk; later sF)
    float* sW  = sPF + 4096;      // 64*64 = 4096
    float* sS  = sW + 4096;       // 256

    int tid = threadIdx.x;
    int gp0 = blockIdx.x << 6;
    int b   = gp0 >> 14;
    int p0  = gp0 & (LTOT - 1);

    // per-(pos,head) scale sqrt(L * attn)
    {
        int pos = tid >> 2, h = tid & 3;
        float e  = g_e[(gp0 + pos) * NHEAD + h];
        sS[tid]  = sqrtf(16384.0f * e / g_sumexp[b * NHEAD + h]);
    }
    __syncthreads();

    // stage scaled t, channel-major: A[c][p], row stride 68
    {
        const float* tb = g_t + (size_t)b * CIN * LTOT + p0;
        #pragma unroll
        for (int e2 = 0; e2 < 8; e2++) {
            int idx = tid + (e2 << 8);
            int c = idx >> 6, p = idx & 63;
            #pragma unroll
            for (int cc = 0; cc < 4; cc++) {
                int c2 = c + (cc << 2);   // 4 channel rows per pass
                A[c2 * 68 + p] = tb[(size_t)c2 * LTOT + p] * sS[(p << 2) + (c2 >> 5)];
            }
            // note: covers c in {0..3,8..11,...}? -> NO. use direct mapping below
        }
    }
    // The loop above is wrong-shaped; redo with a clean single loop:
    __syncthreads();
    {
        const float* tb = g_t + (size_t)b * CIN * LTOT + p0;
        #pragma unroll
        for (int e2 = 0; e2 < 32; e2++) {
            int idx = tid + (e2 << 8);
            int c = idx >> 6, p = idx & 63;
            A[c * 68 + p] = tb[(size_t)c * LTOT + p] * sS[(p << 2) + (c >> 5)];
        }
    }

    // prefetch W chunk 0 into registers
    float4 wreg[4];
    {
        const float4* ws = (const float4*)g_wT;
        #pragma unroll
        for (int i = 0; i < 4; i++) wreg[i] = ws[tid + (i << 8)];
    }

    const int posg = tid & 7;       // 8 pos groups of 8
    const int outg = tid >> 3;      // 32 out groups of 2
    unsigned long long a00 = 0, a01 = 0, a02 = 0, a03 = 0;
    unsigned long long a10 = 0, a11 = 0, a12 = 0, a13 = 0;

    for (int kb = 0; kb < CPOOL; kb += KC) {
        __syncthreads();
        // store prefetched W chunk
        #pragma unroll
        for (int i = 0; i < 4; i++) ((float4*)sW)[tid + (i << 8)] = wreg[i];
        // build pf chunk: pf[k][pos] = t_i[pos] * t_j[pos]
        #pragma unroll
        for (int it = 0; it < 2; it++) {
            int item = tid + (it << 8);
            int kk = item >> 3, oct = item & 7;
            uchar2 ij = g_ij[kb + kk];
            const float* ti = A + (int)ij.x * 68 + (oct << 3);
            const float* tj = A + (int)ij.y * 68 + (oct << 3);
            float4 i0 = *(const float4*)ti;
            float4 i1 = *(const float4*)(ti + 4);
            float4 j0 = *(const float4*)tj;
            float4 j1 = *(const float4*)(tj + 4);
            float4 r0 = make_float4(i0.x * j0.x, i0.y * j0.y, i0.z * j0.z, i0.w * j0.w);
            float4 r1 = make_float4(i1.x * j1.x, i1.y * j1.y, i1.z * j1.z, i1.w * j1.w);
            *(float4*)(sPF + (kk << 6) + (oct << 3))     = r0;
            *(float4*)(sPF + (kk << 6) + (oct << 3) + 4) = r1;
        }
        // prefetch next W chunk (completes during GEMM)
        if (kb + KC < CPOOL) {
            const float4* ws = (const float4*)(g_wT + (kb + KC) * DIMO);
            #pragma unroll
            for (int i = 0; i < 4; i++) wreg[i] = ws[tid + (i << 8)];
        }
        __syncthreads();
        // GEMM over KC: packed f32x2 FMAs
        #pragma unroll 16
        for (int k = 0; k < KC; k++) {
            const float* pr = sPF + (k << 6) + (posg << 3);
            ulonglong2 av0 = *(const ulonglong2*)pr;
            ulonglong2 av1 = *(const ulonglong2*)(pr + 4);
            float2 w = *(const float2*)(sW + (k << 6) + (outg << 1));
            unsigned long long w0 = dup2(w.x);
            unsigned long long w1 = dup2(w.y);
            ffma2(a00, av0.x, w0); ffma2(a01, av0.y, w0);
            ffma2(a02, av1.x, w0); ffma2(a03, av1.y, w0);
            ffma2(a10, av0.x, w1); ffma2(a11, av0.y, w1);
            ffma2(a12, av1.x, w1); ffma2(a13, av1.y, w1);
        }
    }
    __syncthreads();

    // ---- epilogue ----
    // zt[pos][68] in A[0..4351], zo[out][68] in A[4352..8703], sF in sPF area
    {
        int ob0 = outg << 1;
        float d0 = dr_b[ob0], d1 = dr_b[ob0 + 1];
        float2 r;
        int pb = posg << 3;
        r = unpk(a00); A[(pb+0)*68 + ob0] = r.x + d0; A[(pb+1)*68 + ob0] = r.y + d0;
        r = unpk(a01); A[(pb+2)*68 + ob0] = r.x + d0; A[(pb+3)*68 + ob0] = r.y + d0;
        r = unpk(a02); A[(pb+4)*68 + ob0] = r.x + d0; A[(pb+5)*68 + ob0] = r.y + d0;
        r = unpk(a03); A[(pb+6)*68 + ob0] = r.x + d0; A[(pb+7)*68 + ob0] = r.y + d0;
        r = unpk(a10); A[(pb+0)*68 + ob0+1] = r.x + d1; A[(pb+1)*68 + ob0+1] = r.y + d1;
        r = unpk(a11); A[(pb+2)*68 + ob0+1] = r.x + d1; A[(pb+3)*68 + ob0+1] = r.y + d1;
        r = unpk(a12); A[(pb+4)*68 + ob0+1] = r.x + d1; A[(pb+5)*68 + ob0+1] = r.y + d1;
        r = unpk(a13); A[(pb+6)*68 + ob0+1] = r.x + d1; A[(pb+7)*68 + ob0+1] = r.y + d1;
    }
    // stage fc1T into sPF region: sF[c][68]
    #pragma unroll
    for (int e2 = 0; e2 < 16; e2++) {
        int idx = tid + (e2 << 8);
        sPF[(idx >> 6) * 68 + (idx & 63)] = g_fc1T[idx];
    }
    __syncthreads();

    // LayerNorm over 64 channels: 4 threads per position
    {
        int pos = tid >> 2, q = tid & 3;
        float* zr = A + pos * 68 + (q << 4);
        float s = 0.f, s2 = 0.f;
        #pragma unroll
        for (int c = 0; c < 16; c++) { float v = zr[c]; s += v; s2 += v * v; }
        s  += __shfl_xor_sync(0xffffffffu, s, 1);
        s2 += __shfl_xor_sync(0xffffffffu, s2, 1);
        s  += __shfl_xor_sync(0xffffffffu, s, 2);
        s2 += __shfl_xor_sync(0xffffffffu, s2, 2);
        float mu   = s  * (1.0f / 64.0f);
        float var  = s2 * (1.0f / 64.0f) - mu * mu;
        float rstd = rsqrtf(var + 1e-5f);
        #pragma unroll
        for (int c = 0; c < 16; c++) {
            int cc = (q << 4) + c;
            zr[c] = (zr[c] - mu) * rstd * n2w[cc] + n2b[cc];
        }
    }
    __syncthreads();

    // fc1 (64x64) + GELU
    {
        float* zt = A;
        float* sF = sPF;
        float* zo = A + 4352;
        int tx = tid & 15, ty = tid >> 4;
        int tx4 = tx << 2, ty4 = ty << 2;
        float a2[4][4] = {};
        #pragma unroll 8
        for (int c = 0; c < DIMO; c++) {
            float4 f = *(const float4*)(sF + c * 68 + tx4);
            float z0 = zt[(ty4 + 0) * 68 + c];
            float z1 = zt[(ty4 + 1) * 68 + c];
            float z2 = zt[(ty4 + 2) * 68 + c];
            float z3 = zt[(ty4 + 3) * 68 + c];
            a2[0][0] += z0 * f.x; a2[0][1] += z0 * f.y; a2[0][2] += z0 * f.z; a2[0][3] += z0 * f.w;
            a2[1][0] += z1 * f.x; a2[1][1] += z1 * f.y; a2[1][2] += z1 * f.z; a2[1][3] += z1 * f.w;
            a2[2][0] += z2 * f.x; a2[2][1] += z2 * f.y; a2[2][2] += z2 * f.z; a2[2][3] += z2 * f.w;
            a2[3][0] += z3 * f.x; a2[3][1] += z3 * f.y; a2[3][2] += z3 * f.z; a2[3][3] += z3 * f.w;
        }
        #pragma unroll
        for (int r = 0; r < 4; r++)
            #pragma unroll
            for (int j = 0; j < 4; j++) {
                float v = a2[r][j] + fc1_b[tx4 + j];
                v = 0.5f * v * (1.0f + erff(v * 0.70710678118654752f));
                zo[(tx4 + j) * 68 + ty4 + r] = v;
            }
    }
    __syncthreads();

    // coalesced store
    {
        const float* zo = A + 4352;
        float* ob = out + (size_t)b * DIMO * LTOT + p0;
        #pragma unroll
        for (int e2 = 0; e2 < 16; e2++) {
            int idx = tid + (e2 << 8);
            int o = idx >> 6, pos = idx & 63;
            ob[(size_t)o * LTOT + pos] = zo[o * 68 + pos];
        }
    }
}

// ------------------------------- launch -----------------------------------
extern "C" void kernel_launch(void* const* d_in, const int* in_sizes, int n_in,
                              void* d_out, int out_size) {
    const float* x    = (const float*)d_in[0];
    const float* n1w  = (const float*)d_in[1];
    const float* n1b  = (const float*)d_in[2];
    const float* drw  = (const float*)d_in[3];
    const float* drb  = (const float*)d_in[4];
    const float* n2w  = (const float*)d_in[5];
    const float* n2b  = (const float*)d_in[6];
    const float* f1w  = (const float*)d_in[7];
    const float* f1b  = (const float*)d_in[8];
    float* out = (float*)d_out;

    const int SMEM_LN   = (128 * 129 + 3 * 128 + 4) * 4;         // 67600
    const int SMEM_MAIN = (8704 + 4096 + 4096 + 256) * 4;        // 68608

    cudaFuncSetAttribute(k_ln,   cudaFuncAttributeMaxDynamicSharedMemorySize, SMEM_LN);
    cudaFuncSetAttribute(k_main, cudaFuncAttributeMaxDynamicSharedMemorySize, SMEM_MAIN);

    k_init<<<64, 256>>>(drw, f1w);
    k_mid<<<BATCH, 128>>>(x, n1w, n1b);
    k_ln<<<(BATCH * LTOT) / 128, 128, SMEM_LN>>>(x, n1w, n1b);
    k_main<<<(BATCH * LTOT) / 64, 256, SMEM_MAIN>>>(drb, n2w, n2b, f1b, out);
}

// round 9
// speedup vs baseline: 1.6551x; 1.6551x over previous
#include <cuda_runtime.h>
#include <math.h>

// ---------------------------------------------------------------------------
// SPFBlock fused kernel v3, sm_103a
// v3: main GEMM uses 4pos x 8out register tiles (3x LDS.128 per 32 MACs,
// -33% L1 wavefronts vs v1), f32x2 packed FMAs on out-pairs (no dup on W),
// 128-thread blocks, 3 blocks/SM, vectorized pf build, W reg-prefetch.
// ---------------------------------------------------------------------------

#define BATCH   4
#define CIN     128
#define LTOT    16384           // H*W
#define NHEAD   4
#define NPH     32
#define MTRI    528
#define CPOOL   2112
#define DIMO    64
#define KC      64              // 2112 = 33 * 64
#define RS      68              // smem row stride (floats)

// ------------------------- device scratch (static) -------------------------
__device__ float g_t[BATCH * CIN * LTOT];       // shuffled LN'd t, [b][c][pos]
__device__ float g_e[BATCH * LTOT * NHEAD];     // exp(logit)
__device__ float g_wT[CPOOL * DIMO];            // dr_w transposed [k][o]
__device__ float g_fc1T[DIMO * DIMO];           // fc1_w transposed [c][j]
__device__ float g_umid[BATCH * CIN];           // t at mid, shuffled order
__device__ float g_invnmid[BATCH * NHEAD];      // 1/||y_mid||
__device__ float g_sumexp[BATCH * NHEAD];       // softmax denominators
__device__ uchar2 g_ij[CPOOL];                  // tri indices (i,j) + head off

// ------------------------------ f32x2 helpers ------------------------------
__device__ __forceinline__ unsigned long long dup2(float x) {
    unsigned long long r;
    asm("mov.b64 %0, {%1, %1};" : "=l"(r) : "f"(x));
    return r;
}
__device__ __forceinline__ void ffma2(unsigned long long& acc,
                                      unsigned long long a,
                                      unsigned long long b) {
    asm("fma.rn.f32x2 %0, %1, %2, %0;" : "+l"(acc) : "l"(a), "l"(b));
}
__device__ __forceinline__ float2 unpk(unsigned long long v) {
    float2 r;
    asm("mov.b64 {%0, %1}, %2;" : "=f"(r.x), "=f"(r.y) : "l"(v));
    return r;
}

// ------------------------------- init kernel -------------------------------
__global__ void k_init(const float* __restrict__ dr_w,
                       const float* __restrict__ fc1_w) {
    int tid = blockIdx.x * blockDim.x + threadIdx.x;
    int nth = gridDim.x * blockDim.x;
    for (int idx = tid; idx < CPOOL * DIMO; idx += nth) {
        int k = idx >> 6, o = idx & 63;
        g_wT[idx] = dr_w[o * CPOOL + k];
    }
    for (int idx = tid; idx < DIMO * DIMO; idx += nth) {
        int c = idx >> 6, j = idx & 63;
        g_fc1T[idx] = fc1_w[j * DIMO + c];
    }
    if (blockIdx.x == 0) {
        for (int m = threadIdx.x; m < MTRI; m += blockDim.x) {
            int i = 0, off = 0;
            while (off + (NPH - i) <= m) { off += NPH - i; i++; }
            int j = i + (m - off);
            #pragma unroll
            for (int h = 0; h < NHEAD; h++) {
                uchar2 v;
                v.x = (unsigned char)(h * NPH + i);
                v.y = (unsigned char)(h * NPH + j);
                g_ij[h * MTRI + m] = v;
            }
        }
        if (threadIdx.x < BATCH * NHEAD) g_sumexp[threadIdx.x] = 0.0f;
    }
}

// ------------------------------- mid kernel --------------------------------
__global__ void k_mid(const float* __restrict__ x,
                      const float* __restrict__ n1w,
                      const float* __restrict__ n1b) {
    __shared__ float red[CIN];
    __shared__ float us[CIN];
    int b = blockIdx.x, tid = threadIdx.x;
    float v = x[((size_t)b * CIN + tid) * LTOT + (LTOT / 2)];
    red[tid] = v;
    __syncthreads();
    for (int o = 64; o; o >>= 1) { if (tid < o) red[tid] += red[tid + o]; __syncthreads(); }
    float mu = red[0] * (1.0f / 128.0f);
    __syncthreads();
    red[tid] = v * v;
    __syncthreads();
    for (int o = 64; o; o >>= 1) { if (tid < o) red[tid] += red[tid + o]; __syncthreads(); }
    float var = red[0] * (1.0f / 128.0f) - mu * mu;
    float rstd = rsqrtf(var + 1e-5f);
    float xn = (v - mu) * rstd * n1w[tid] + n1b[tid];
    int cp = ((tid & 3) << 5) + (tid >> 2);          // shuffled channel
    us[cp] = xn;
    g_umid[b * CIN + cp] = xn;
    __syncthreads();
    if (tid < NHEAD) {
        float uu = 0.f, s4 = 0.f;
        #pragma unroll
        for (int i = 0; i < NPH; i++) {
            float u = us[tid * NPH + i];
            float u2 = u * u;
            uu += u2; s4 += u2 * u2;
        }
        g_invnmid[b * NHEAD + tid] = rsqrtf(0.5f * (uu * uu + s4));
    }
}

// -------------------------------- LN kernel --------------------------------
// 128 positions per block; stores t CHANNEL-MAJOR.
__global__ void k_ln(const float* __restrict__ x,
                     const float* __restrict__ n1w,
                     const float* __restrict__ n1b) {
    extern __shared__ float sm[];
    float* xs   = sm;                       // 128*129
    float* su   = sm + 128 * 129;           // 128
    float* swv  = su + 128;                 // 128
    float* sbv  = swv + 128;                // 128
    float* sAcc = sbv + 128;                // 4

    int tid = threadIdx.x;
    int blk = blockIdx.x;
    int b   = blk >> 7;
    int p0  = (blk & 127) << 7;

    su[tid] = g_umid[b * CIN + tid];
    {
        int c = ((tid & 31) << 2) + (tid >> 5);   // inverse shuffle
        swv[tid] = n1w[c];
        sbv[tid] = n1b[c];
    }
    if (tid < NHEAD) sAcc[tid] = 0.0f;

    const float* xb = x + (size_t)b * CIN * LTOT + p0;
    #pragma unroll 4
    for (int cc = 0; cc < CIN; cc++) {
        float v = xb[(size_t)cc * LTOT + tid];
        int cp = ((cc & 3) << 5) + (cc >> 2);
        xs[tid * 129 + cp] = v;
    }
    __syncthreads();

    float* row = xs + tid * 129;
    float s = 0.f, s2 = 0.f;
    #pragma unroll 8
    for (int c = 0; c < CIN; c++) { float v = row[c]; s += v; s2 += v * v; }
    float mu   = s  * (1.0f / 128.0f);
    float var  = s2 * (1.0f / 128.0f) - mu * mu;
    float rstd = rsqrtf(var + 1e-5f);

    int gp = b * LTOT + p0 + tid;
    #pragma unroll
    for (int h = 0; h < NHEAD; h++) {
        float duv = 0.f, dvv = 0.f, suv = 0.f, sv4 = 0.f;
        #pragma unroll 8
        for (int i = 0; i < NPH; i++) {
            int c = h * NPH + i;
            float v = (row[c] - mu) * rstd * swv[c] + sbv[c];
            row[c] = v;
            float u  = su[c];
            float uv = u * v;
            float v2 = v * v;
            duv += uv;
            dvv += v2;
            suv += uv * uv;
            sv4 += v2 * v2;
        }
        float ny2   = 0.5f * (dvv * dvv + sv4);
        float logit = 0.5f * (duv * duv + suv) * rsqrtf(ny2) * g_invnmid[b * NHEAD + h];
        float e = expf(logit);
        g_e[gp * NHEAD + h] = e;
        float we = e;
        #pragma unroll
        for (int o = 16; o; o >>= 1) we += __shfl_xor_sync(0xffffffffu, we, o);
        if ((tid & 31) == 0) atomicAdd(&sAcc[h], we);
    }
    __syncthreads();
    if (tid < NHEAD) atomicAdd(&g_sumexp[b * NHEAD + tid], sAcc[tid]);

    // channel-major coalesced store
    float* tb = g_t + (size_t)b * CIN * LTOT + p0;
    #pragma unroll 4
    for (int c = 0; c < CIN; c++) {
        tb[(size_t)c * LTOT + tid] = xs[tid * 129 + c];
    }
}

// ------------------------------- main kernel -------------------------------
// 64 pos x 64 out per block, 128 threads. Thread tile: 4 pos x 8 out.
// Accumulators: f32x2 out-pairs (W loaded packed, only p duplicated).
__global__ __launch_bounds__(128, 3) void k_main(const float* __restrict__ dr_b,
                                                 const float* __restrict__ n2w,
                                                 const float* __restrict__ n2b,
                                                 const float* __restrict__ fc1_b,
                                                 float* __restrict__ out) {
    extern __shared__ float sm[];
    float* A   = sm;                 // sTc [c][pos] 128*RS = 8704 (later zt/zo)
    float* sPF = sm + 8704;          // [k][pos]  64*RS = 4352 (later sF)
    float* sW  = sPF + 4352;         // [k][out]  64*RS = 4352
    float* sS  = sW + 4352;          // 256
    uchar2* sIJ = (uchar2*)(sS + 256);   // 2112 uchar2 = 4224 B

    int tid = threadIdx.x;
    int gp0 = blockIdx.x << 6;
    int b   = gp0 >> 14;
    int p0  = gp0 & (LTOT - 1);

    // per-(pos,head) scale sqrt(L * attn)
    #pragma unroll
    for (int it = 0; it < 2; it++) {
        int idx = tid + (it << 7);
        int pos = idx >> 2, h = idx & 3;
        float e = g_e[(gp0 + pos) * NHEAD + h];
        sS[idx] = sqrtf(16384.0f * e / g_sumexp[b * NHEAD + h]);
    }
    for (int idx = tid; idx < CPOOL; idx += 128) sIJ[idx] = g_ij[idx];
    __syncthreads();

    // stage scaled t, channel-major: A[c][p]
    {
        const float* tb = g_t + (size_t)b * CIN * LTOT + p0;
        #pragma unroll
        for (int it = 0; it < 64; it++) {
            int idx = tid + (it << 7);
            int c = idx >> 6, p = idx & 63;
            A[c * RS + p] = tb[(size_t)c * LTOT + p] * sS[(p << 2) + (c >> 5)];
        }
    }

    // prefetch W chunk 0 into registers (8 x float4 per thread)
    float4 wreg[8];
    {
        const float4* ws = (const float4*)g_wT;
        #pragma unroll
        for (int i = 0; i < 8; i++) wreg[i] = ws[tid + (i << 7)];
    }

    const int tx = tid & 7;          // out octet: tx*8 .. tx*8+7
    const int ty = tid >> 3;         // pos quad:  ty*4 .. ty*4+3
    const int kkb = tid >> 1;        // pf-build k row
    const int pf_half = (tid & 1) << 5;

    unsigned long long acc[4][4];
    #pragma unroll
    for (int r = 0; r < 4; r++)
        #pragma unroll
        for (int q = 0; q < 4; q++) acc[r][q] = 0ull;

    for (int kb = 0; kb < CPOOL; kb += KC) {
        __syncthreads();
        // store prefetched W chunk: [k][out], row stride RS
        #pragma unroll
        for (int i = 0; i < 8; i++) {
            int idx = tid + (i << 7);           // 0..1023 of float4s
            int k = idx >> 4, c4 = (idx & 15) << 2;
            *(float4*)(sW + k * RS + c4) = wreg[i];
        }
        // build pf chunk (vectorized over pos): pf[k][p] = t_i[p]*t_j[p]
        {
            uchar2 ij = sIJ[kb + kkb];
            const float* ti = A + (int)ij.x * RS + pf_half;
            const float* tj = A + (int)ij.y * RS + pf_half;
            float* pd = sPF + kkb * RS + pf_half;
            #pragma unroll
            for (int q = 0; q < 8; q++) {
                float4 a4 = *(const float4*)(ti + (q << 2));
                float4 b4 = *(const float4*)(tj + (q << 2));
                *(float4*)(pd + (q << 2)) = make_float4(a4.x * b4.x, a4.y * b4.y,
                                                        a4.z * b4.z, a4.w * b4.w);
            }
        }
        // prefetch next W chunk
        if (kb + KC < CPOOL) {
            const float4* ws = (const float4*)(g_wT + (kb + KC) * DIMO);
            #pragma unroll
            for (int i = 0; i < 8; i++) wreg[i] = ws[tid + (i << 7)];
        }
        __syncthreads();
        // GEMM over KC
        #pragma unroll 8
        for (int k = 0; k < KC; k++) {
            float4 p = *(const float4*)(sPF + k * RS + (ty << 2));
            ulonglong2 w0 = *(const ulonglong2*)(sW + k * RS + (tx << 3));
            ulonglong2 w1 = *(const ulonglong2*)(sW + k * RS + (tx << 3) + 4);
            unsigned long long p0d = dup2(p.x), p1d = dup2(p.y);
            unsigned long long p2d = dup2(p.z), p3d = dup2(p.w);
            ffma2(acc[0][0], p0d, w0.x); ffma2(acc[0][1], p0d, w0.y);
            ffma2(acc[0][2], p0d, w1.x); ffma2(acc[0][3], p0d, w1.y);
            ffma2(acc[1][0], p1d, w0.x); ffma2(acc[1][1], p1d, w0.y);
            ffma2(acc[1][2], p1d, w1.x); ffma2(acc[1][3], p1d, w1.y);
            ffma2(acc[2][0], p2d, w0.x); ffma2(acc[2][1], p2d, w0.y);
            ffma2(acc[2][2], p2d, w1.x); ffma2(acc[2][3], p2d, w1.y);
            ffma2(acc[3][0], p3d, w0.x); ffma2(acc[3][1], p3d, w0.y);
            ffma2(acc[3][2], p3d, w1.x); ffma2(acc[3][3], p3d, w1.y);
        }
    }
    __syncthreads();

    // ---- epilogue: +dr_b, LayerNorm(64), fc1(64x64), GELU(exact), store ----
    float* zt = A;                      // [pos][RS], 64 rows
    float* zo = A + 64 * RS;            // [out][RS]... reuse upper half of A
    {
        int ob = tx << 3;
        #pragma unroll
        for (int r = 0; r < 4; r++) {
            int pos = (ty << 2) + r;
            #pragma unroll
            for (int q = 0; q < 4; q++) {
                float2 v = unpk(acc[r][q]);
                int o = ob + (q << 1);
                zt[pos * RS + o]     = v.x + dr_b[o];
                zt[pos * RS + o + 1] = v.y + dr_b[o + 1];
            }
        }
    }
    // stage fc1T into sPF region: sF[c][RS]
    #pragma unroll
    for (int it = 0; it < 32; it++) {
        int idx = tid + (it << 7);
        sPF[(idx >> 6) * RS + (idx & 63)] = g_fc1T[idx];
    }
    __syncthreads();

    // LayerNorm over 64 channels: 2 threads per position
    {
        int pos = tid >> 1, half = (tid & 1) << 5;
        float* zr = zt + pos * RS + half;
        float s = 0.f, s2 = 0.f;
        #pragma unroll
        for (int c = 0; c < 32; c++) { float v = zr[c]; s += v; s2 += v * v; }
        s  += __shfl_xor_sync(0xffffffffu, s, 1);
        s2 += __shfl_xor_sync(0xffffffffu, s2, 1);
        float mu   = s  * (1.0f / 64.0f);
        float var  = s2 * (1.0f / 64.0f) - mu * mu;
        float rstd = rsqrtf(var + 1e-5f);
        #pragma unroll
        for (int c = 0; c < 32; c++) {
            int cc = half + c;
            zr[c] = (zr[c] - mu) * rstd * n2w[cc] + n2b[cc];
        }
    }
    __syncthreads();

    // fc1 (64x64) + GELU: thread tile 8 pos x 4 out
    {
        float* sF = sPF;
        int tx2 = tid & 15, ty2 = tid >> 4;
        int ob = tx2 << 2, pb = ty2 << 3;
        float a2[8][4];
        #pragma unroll
        for (int r = 0; r < 8; r++)
            #pragma unroll
            for (int j = 0; j < 4; j++) a2[r][j] = 0.f;
        #pragma unroll 8
        for (int c = 0; c < DIMO; c++) {
            float4 f = *(const float4*)(sF + c * RS + ob);
            #pragma unroll
            for (int r = 0; r < 8; r++) {
                float z = zt[(pb + r) * RS + c];
                a2[r][0] += z * f.x; a2[r][1] += z * f.y;
                a2[r][2] += z * f.z; a2[r][3] += z * f.w;
            }
        }
        #pragma unroll
        for (int r = 0; r < 8; r++)
            #pragma unroll
            for (int j = 0; j < 4; j++) {
                float v = a2[r][j] + fc1_b[ob + j];
                v = 0.5f * v * (1.0f + erff(v * 0.70710678118654752f));
                zo[(ob + j) * RS + pb + r] = v;
            }
    }
    __syncthreads();

    // coalesced store
    {
        float* ob = out + (size_t)b * DIMO * LTOT + p0;
        #pragma unroll
        for (int it = 0; it < 32; it++) {
            int idx = tid + (it << 7);
            int o = idx >> 6, pos = idx & 63;
            ob[(size_t)o * LTOT + pos] = zo[o * RS + pos];
        }
    }
}

// ------------------------------- launch -----------------------------------
extern "C" void kernel_launch(void* const* d_in, const int* in_sizes, int n_in,
                              void* d_out, int out_size) {
    const float* x    = (const float*)d_in[0];
    const float* n1w  = (const float*)d_in[1];
    const float* n1b  = (const float*)d_in[2];
    const float* drw  = (const float*)d_in[3];
    const float* drb  = (const float*)d_in[4];
    const float* n2w  = (const float*)d_in[5];
    const float* n2b  = (const float*)d_in[6];
    const float* f1w  = (const float*)d_in[7];
    const float* f1b  = (const float*)d_in[8];
    float* out = (float*)d_out;

    const int SMEM_LN   = (128 * 129 + 3 * 128 + 4) * 4;              // 67600
    const int SMEM_MAIN = (8704 + 4352 + 4352 + 256) * 4 + CPOOL * 2; // 74880

    cudaFuncSetAttribute(k_ln,   cudaFuncAttributeMaxDynamicSharedMemorySize, SMEM_LN);
    cudaFuncSetAttribute(k_main, cudaFuncAttributeMaxDynamicSharedMemorySize, SMEM_MAIN);

    k_init<<<64, 256>>>(drw, f1w);
    k_mid<<<BATCH, 128>>>(x, n1w, n1b);
    k_ln<<<(BATCH * LTOT) / 128, 128, SMEM_LN>>>(x, n1w, n1b);
    k_main<<<(BATCH * LTOT) / 64, 128, SMEM_MAIN>>>(drb, n2w, n2b, f1b, out);
}

// round 11
// speedup vs baseline: 4.1460x; 2.5049x over previous
#include <cuda_runtime.h>
#include <math.h>
#include <stdint.h>

// ---------------------------------------------------------------------------
// SPFBlock fused kernel v5, sm_103 (portable PTX) — tensor-core main GEMM via
// mma.sync.m16n8k8 tf32 (sm_80+ baseline; tcgen05 unavailable: harness ptxas
// targets compute_103 without the 'a' suffix).
// pf[M][K=2112] built on the fly into smem (tf32), dr_w^T chunks in smem,
// fp32 register accumulation, fused +bias/LN/fc1/GELU epilogue.
// ---------------------------------------------------------------------------

#define BATCH   4
#define CIN     128
#define LTOT    16384
#define NHEAD   4
#define NPH     32
#define MTRI    528
#define CPOOL   2112
#define DIMO    64
#define NCHUNK  33              // 33 * 64 = 2112

// smem float offsets (k_main)
#define FT      0               // t tile [128c][128p]            16384
#define FPF     16384           // pf [64k][136] (later zt[128][68]) 8704
#define FB      25088           // B  [64k][72]                    4608
#define FS      29696           // scales 512
#define FP      30208           // params 256
#define FIJ     30464           // ij table 4224 B = 1056 floats
#define FTOT    31520           // 126080 bytes

// ------------------------- device scratch (static) -------------------------
__device__ float g_t[BATCH * CIN * LTOT];       // shuffled LN'd t, [b][c][pos]
__device__ float g_e[BATCH * LTOT * NHEAD];     // exp(logit)
__device__ float g_wTk[CPOOL * DIMO];           // dr_w, k-major, tf32-rounded
__device__ float g_fc1T[DIMO * DIMO];           // fc1_w transposed [c][j]
__device__ float g_umid[BATCH * CIN];
__device__ float g_invnmid[BATCH * NHEAD];
__device__ float g_sumexp[BATCH * NHEAD];
__device__ uchar2 g_ij[CPOOL];

// ------------------------------ PTX helpers --------------------------------
__device__ __forceinline__ uint32_t cvt_tf32(float x) {
    uint32_t r;
    asm("cvt.rna.tf32.f32 %0, %1;" : "=r"(r) : "f"(x));
    return r;
}
__device__ __forceinline__ void mma8(float* d, const uint32_t* a, const uint32_t* b) {
    asm volatile(
        "mma.sync.aligned.m16n8k8.row.col.f32.tf32.tf32.f32 "
        "{%0,%1,%2,%3}, {%4,%5,%6,%7}, {%8,%9}, {%0,%1,%2,%3};"
        : "+f"(d[0]), "+f"(d[1]), "+f"(d[2]), "+f"(d[3])
        : "r"(a[0]), "r"(a[1]), "r"(a[2]), "r"(a[3]), "r"(b[0]), "r"(b[1]));
}

// ------------------------------- init kernel -------------------------------
__global__ void k_init(const float* __restrict__ dr_w,
                       const float* __restrict__ fc1_w) {
    int tid = blockIdx.x * blockDim.x + threadIdx.x;
    int nth = gridDim.x * blockDim.x;
    // k-major, tf32-rounded dr_w: g_wTk[k][o]
    for (int idx = tid; idx < CPOOL * DIMO; idx += nth) {
        int k = idx >> 6, o = idx & 63;
        g_wTk[idx] = __uint_as_float(cvt_tf32(dr_w[o * CPOOL + k]));
    }
    for (int idx = tid; idx < DIMO * DIMO; idx += nth) {
        int c = idx >> 6, j = idx & 63;
        g_fc1T[idx] = fc1_w[j * DIMO + c];
    }
    if (blockIdx.x == 0) {
        for (int m = threadIdx.x; m < MTRI; m += blockDim.x) {
            int i = 0, off = 0;
            while (off + (NPH - i) <= m) { off += NPH - i; i++; }
            int j = i + (m - off);
            #pragma unroll
            for (int h = 0; h < NHEAD; h++) {
                uchar2 v;
                v.x = (unsigned char)(h * NPH + i);
                v.y = (unsigned char)(h * NPH + j);
                g_ij[h * MTRI + m] = v;
            }
        }
        if (threadIdx.x < BATCH * NHEAD) g_sumexp[threadIdx.x] = 0.0f;
    }
}

// ------------------------------- mid kernel --------------------------------
__global__ void k_mid(const float* __restrict__ x,
                      const float* __restrict__ n1w,
                      const float* __restrict__ n1b) {
    __shared__ float red[CIN];
    __shared__ float us[CIN];
    int b = blockIdx.x, tid = threadIdx.x;
    float v = x[((size_t)b * CIN + tid) * LTOT + (LTOT / 2)];
    red[tid] = v;
    __syncthreads();
    for (int o = 64; o; o >>= 1) { if (tid < o) red[tid] += red[tid + o]; __syncthreads(); }
    float mu = red[0] * (1.0f / 128.0f);
    __syncthreads();
    red[tid] = v * v;
    __syncthreads();
    for (int o = 64; o; o >>= 1) { if (tid < o) red[tid] += red[tid + o]; __syncthreads(); }
    float var = red[0] * (1.0f / 128.0f) - mu * mu;
    float rstd = rsqrtf(var + 1e-5f);
    float xn = (v - mu) * rstd * n1w[tid] + n1b[tid];
    int cp = ((tid & 3) << 5) + (tid >> 2);
    us[cp] = xn;
    g_umid[b * CIN + cp] = xn;
    __syncthreads();
    if (tid < NHEAD) {
        float uu = 0.f, s4 = 0.f;
        #pragma unroll
        for (int i = 0; i < NPH; i++) {
            float u = us[tid * NPH + i];
            float u2 = u * u;
            uu += u2; s4 += u2 * u2;
        }
        g_invnmid[b * NHEAD + tid] = rsqrtf(0.5f * (uu * uu + s4));
    }
}

// -------------------------------- LN kernel --------------------------------
__global__ void k_ln(const float* __restrict__ x,
                     const float* __restrict__ n1w,
                     const float* __restrict__ n1b) {
    extern __shared__ float sm[];
    float* xs   = sm;                       // 128*129
    float* su   = sm + 128 * 129;
    float* swv  = su + 128;
    float* sbv  = swv + 128;
    float* sAcc = sbv + 128;

    int tid = threadIdx.x;
    int blk = blockIdx.x;
    int b   = blk >> 7;
    int p0  = (blk & 127) << 7;

    su[tid] = g_umid[b * CIN + tid];
    {
        int c = ((tid & 31) << 2) + (tid >> 5);
        swv[tid] = n1w[c];
        sbv[tid] = n1b[c];
    }
    if (tid < NHEAD) sAcc[tid] = 0.0f;

    const float* xb = x + (size_t)b * CIN * LTOT + p0;
    #pragma unroll 4
    for (int cc = 0; cc < CIN; cc++) {
        float v = xb[(size_t)cc * LTOT + tid];
        int cp = ((cc & 3) << 5) + (cc >> 2);
        xs[tid * 129 + cp] = v;
    }
    __syncthreads();

    float* row = xs + tid * 129;
    float s = 0.f, s2 = 0.f;
    #pragma unroll 8
    for (int c = 0; c < CIN; c++) { float v = row[c]; s += v; s2 += v * v; }
    float mu   = s  * (1.0f / 128.0f);
    float var  = s2 * (1.0f / 128.0f) - mu * mu;
    float rstd = rsqrtf(var + 1e-5f);

    int gp = b * LTOT + p0 + tid;
    #pragma unroll
    for (int h = 0; h < NHEAD; h++) {
        float duv = 0.f, dvv = 0.f, suv = 0.f, sv4 = 0.f;
        #pragma unroll 8
        for (int i = 0; i < NPH; i++) {
            int c = h * NPH + i;
            float v = (row[c] - mu) * rstd * swv[c] + sbv[c];
            row[c] = v;
            float u  = su[c];
            float uv = u * v;
            float v2 = v * v;
            duv += uv; dvv += v2; suv += uv * uv; sv4 += v2 * v2;
        }
        float ny2   = 0.5f * (dvv * dvv + sv4);
        float logit = 0.5f * (duv * duv + suv) * rsqrtf(ny2) * g_invnmid[b * NHEAD + h];
        float e = expf(logit);
        g_e[gp * NHEAD + h] = e;
        float we = e;
        #pragma unroll
        for (int o = 16; o; o >>= 1) we += __shfl_xor_sync(0xffffffffu, we, o);
        if ((tid & 31) == 0) atomicAdd(&sAcc[h], we);
    }
    __syncthreads();
    if (tid < NHEAD) atomicAdd(&g_sumexp[b * NHEAD + tid], sAcc[tid]);

    float* tb = g_t + (size_t)b * CIN * LTOT + p0;
    #pragma unroll 4
    for (int c = 0; c < CIN; c++) {
        tb[(size_t)c * LTOT + tid] = xs[tid * 129 + c];
    }
}

// ------------------------------- main kernel -------------------------------
// 128 pos x 64 out per block, 256 threads (8 warps).
// Warp w: pos base (w&3)*32, n base (w>>2)*32; 2 m16 x 4 n8 mma tiles.
__global__ __launch_bounds__(256, 1)
void k_main(const float* __restrict__ dr_b,  const float* __restrict__ n2w,
            const float* __restrict__ n2b,   const float* __restrict__ fc1_b,
            float* __restrict__ out) {
    extern __shared__ float sm[];
    float*  sT  = sm + FT;
    float*  sPF = sm + FPF;
    float*  sB  = sm + FB;
    float*  sS  = sm + FS;
    float*  sP  = sm + FP;
    uchar2* sIJ = (uchar2*)(sm + FIJ);

    int tid  = threadIdx.x;
    int lane = tid & 31, w = tid >> 5;
    int gp0  = blockIdx.x << 7;
    int b    = gp0 >> 14;
    int p0   = gp0 & (LTOT - 1);

    // stage scales sqrt(L*attn), ij table, params
    #pragma unroll
    for (int it = 0; it < 2; it++) {
        int idx = tid + (it << 8);
        int pos = idx >> 2, h = idx & 3;
        float e = g_e[(gp0 + pos) * NHEAD + h];
        sS[idx] = sqrtf(16384.0f * e / g_sumexp[b * NHEAD + h]);
    }
    for (int idx = tid; idx < CPOOL / 2; idx += 256)
        ((uint32_t*)sIJ)[idx] = ((const uint32_t*)g_ij)[idx];
    if (tid < 64) {
        sP[tid]       = dr_b[tid];
        sP[64 + tid]  = n2w[tid];
        sP[128 + tid] = n2b[tid];
        sP[192 + tid] = fc1_b[tid];
    }
    __syncthreads();

    // stage scaled t [c][pos], stride 128
    {
        const float* tb = g_t + (size_t)b * CIN * LTOT + p0;
        #pragma unroll
        for (int it = 0; it < 16; it++) {
            int idx = tid + (it << 8);
            int c = idx >> 5, p4 = (idx & 31) << 2;
            float4 v = *(const float4*)(tb + (size_t)c * LTOT + p4);
            int hb = c >> 5;
            v.x *= sS[((p4 + 0) << 2) + hb];
            v.y *= sS[((p4 + 1) << 2) + hb];
            v.z *= sS[((p4 + 2) << 2) + hb];
            v.w *= sS[((p4 + 3) << 2) + hb];
            *(float4*)(sT + (c << 7) + p4) = v;
        }
    }

    // prefetch B chunk 0 (1024 float4 / 256 thr = 4 each)
    float4 breg[4];
    {
        const float4* ws = (const float4*)g_wTk;
        #pragma unroll
        for (int i = 0; i < 4; i++) breg[i] = ws[tid + (i << 8)];
    }

    const int tig = lane & 3, gid = lane >> 2;
    const int pbase = (w & 3) << 5;
    const int nbase = (w >> 2) << 5;

    float d[2][4][4];
    #pragma unroll
    for (int mt = 0; mt < 2; mt++)
        #pragma unroll
        for (int nt = 0; nt < 4; nt++)
            #pragma unroll
            for (int q = 0; q < 4; q++) d[mt][nt][q] = 0.f;

    __syncthreads();

    uint32_t* pfu = (uint32_t*)sPF;
    for (int g = 0; g < NCHUNK; g++) {
        int kbase = g << 6;
        // store prefetched B chunk: [k][72]
        #pragma unroll
        for (int i = 0; i < 4; i++) {
            int idx = tid + (i << 8);
            int k = idx >> 4, n4 = (idx & 15) << 2;
            *(float4*)(sB + k * 72 + n4) = breg[i];
        }
        // build pf rows: 8 rows per warp, full 128-pos row per lane-pass
        #pragma unroll
        for (int rr = 0; rr < 8; rr++) {
            int rw = (w << 3) + rr;
            uchar2 ij = sIJ[kbase + rw];
            const float* ti = sT + ((int)ij.x << 7);
            const float* tj = sT + ((int)ij.y << 7);
            int p4 = lane << 2;
            float4 a4 = *(const float4*)(ti + p4);
            float4 b4 = *(const float4*)(tj + p4);
            uint4 r;
            r.x = cvt_tf32(a4.x * b4.x);
            r.y = cvt_tf32(a4.y * b4.y);
            r.z = cvt_tf32(a4.z * b4.z);
            r.w = cvt_tf32(a4.w * b4.w);
            *(uint4*)(pfu + rw * 136 + p4) = r;
        }
        __syncthreads();
        // prefetch next B chunk during mma
        if (g + 1 < NCHUNK) {
            const float4* ws = (const float4*)(g_wTk + (kbase + 64) * DIMO);
            #pragma unroll
            for (int i = 0; i < 4; i++) breg[i] = ws[tid + (i << 8)];
        }
        // mma over 8 k8 steps
        #pragma unroll
        for (int kk = 0; kk < 8; kk++) {
            int k0 = kk << 3;
            uint32_t a[2][4];
            #pragma unroll
            for (int mt = 0; mt < 2; mt++) {
                int pr = pbase + (mt << 4) + gid;
                a[mt][0] = pfu[(k0 + tig) * 136 + pr];
                a[mt][1] = pfu[(k0 + tig) * 136 + pr + 8];
                a[mt][2] = pfu[(k0 + 4 + tig) * 136 + pr];
                a[mt][3] = pfu[(k0 + 4 + tig) * 136 + pr + 8];
            }
            uint32_t bb[4][2];
            #pragma unroll
            for (int nt = 0; nt < 4; nt++) {
                int nc = nbase + (nt << 3) + gid;
                bb[nt][0] = __float_as_uint(sB[(k0 + tig) * 72 + nc]);
                bb[nt][1] = __float_as_uint(sB[(k0 + 4 + tig) * 72 + nc]);
            }
            #pragma unroll
            for (int mt = 0; mt < 2; mt++)
                #pragma unroll
                for (int nt = 0; nt < 4; nt++)
                    mma8(d[mt][nt], a[mt], bb[nt]);
        }
        __syncthreads();
    }

    // ---- epilogue ----
    // zt[pos][68] occupies the pf region (exactly 8704 floats)
    float* zt = sPF;
    #pragma unroll
    for (int mt = 0; mt < 2; mt++) {
        int r0 = pbase + (mt << 4) + gid;
        #pragma unroll
        for (int nt = 0; nt < 4; nt++) {
            int col = nbase + (nt << 3) + (tig << 1);
            zt[r0 * 68 + col]           = d[mt][nt][0] + sP[col];
            zt[r0 * 68 + col + 1]       = d[mt][nt][1] + sP[col + 1];
            zt[(r0 + 8) * 68 + col]     = d[mt][nt][2] + sP[col];
            zt[(r0 + 8) * 68 + col + 1] = d[mt][nt][3] + sP[col + 1];
        }
    }
    // stage fc1T into t region: sF[c][68]; zo later at sT+4400 [o][132]
    float* sF = sT;
    float* zo = sT + 4400;
    #pragma unroll
    for (int it = 0; it < 16; it++) {
        int idx = tid + (it << 8);
        sF[(idx >> 6) * 68 + (idx & 63)] = g_fc1T[idx];
    }
    __syncthreads();

    // LayerNorm over 64 channels: 2 threads per position
    {
        int pos = tid >> 1, half = (tid & 1) << 5;
        float* zr = zt + pos * 68 + half;
        float s = 0.f, s2 = 0.f;
        #pragma unroll
        for (int c = 0; c < 32; c++) { float v = zr[c]; s += v; s2 += v * v; }
        s  += __shfl_xor_sync(0xffffffffu, s, 1);
        s2 += __shfl_xor_sync(0xffffffffu, s2, 1);
        float mu   = s  * (1.0f / 64.0f);
        float var  = s2 * (1.0f / 64.0f) - mu * mu;
        float rstd = rsqrtf(var + 1e-5f);
        #pragma unroll
        for (int c = 0; c < 32; c++) {
            int cc = half + c;
            zr[c] = (zr[c] - mu) * rstd * sP[64 + cc] + sP[128 + cc];
        }
    }
    __syncthreads();

    // fc1 (64x64) + GELU: thread tile 8 pos x 4 out
    {
        int tx = tid & 15, ty = tid >> 4;
        int ob = tx << 2, pb = ty << 3;
        float a2[8][4];
        #pragma unroll
        for (int r = 0; r < 8; r++)
            #pragma unroll
            for (int j = 0; j < 4; j++) a2[r][j] = 0.f;
        #pragma unroll 8
        for (int c = 0; c < DIMO; c++) {
            float4 f = *(const float4*)(sF + c * 68 + ob);
            #pragma unroll
            for (int r = 0; r < 8; r++) {
                float z = zt[(pb + r) * 68 + c];
                a2[r][0] += z * f.x; a2[r][1] += z * f.y;
                a2[r][2] += z * f.z; a2[r][3] += z * f.w;
            }
        }
        #pragma unroll
        for (int r = 0; r < 8; r++)
            #pragma unroll
            for (int j = 0; j < 4; j++) {
                float v = a2[r][j] + sP[192 + ob + j];
                v = 0.5f * v * (1.0f + erff(v * 0.70710678118654752f));
                zo[(ob + j) * 132 + pb + r] = v;
            }
    }
    __syncthreads();

    // coalesced store
    {
        float* ob = out + (size_t)b * DIMO * LTOT + p0;
        #pragma unroll
        for (int it = 0; it < 32; it++) {
            int idx = tid + (it << 8);
            int o = idx >> 7, pos = idx & 127;
            ob[(size_t)o * LTOT + pos] = zo[o * 132 + pos];
        }
    }
}

// ------------------------------- launch -----------------------------------
extern "C" void kernel_launch(void* const* d_in, const int* in_sizes, int n_in,
                              void* d_out, int out_size) {
    const float* x    = (const float*)d_in[0];
    const float* n1w  = (const float*)d_in[1];
    const float* n1b  = (const float*)d_in[2];
    const float* drw  = (const float*)d_in[3];
    const float* drb  = (const float*)d_in[4];
    const float* n2w  = (const float*)d_in[5];
    const float* n2b  = (const float*)d_in[6];
    const float* f1w  = (const float*)d_in[7];
    const float* f1b  = (const float*)d_in[8];
    float* out = (float*)d_out;

    const int SMEM_LN   = (128 * 129 + 3 * 128 + 4) * 4;   // 67600
    const int SMEM_MAIN = FTOT * 4;                        // 126080

    cudaFuncSetAttribute(k_ln,   cudaFuncAttributeMaxDynamicSharedMemorySize, SMEM_LN);
    cudaFuncSetAttribute(k_main, cudaFuncAttributeMaxDynamicSharedMemorySize, SMEM_MAIN);

    k_init<<<64, 256>>>(drw, f1w);
    k_mid<<<BATCH, 128>>>(x, n1w, n1b);
    k_ln<<<(BATCH * LTOT) / 128, 128, SMEM_LN>>>(x, n1w, n1b);
    k_main<<<(BATCH * LTOT) / 128, 256, SMEM_MAIN>>>(drb, n2w, n2b, f1b, out);
}